// round 8
// baseline (speedup 1.0000x reference)
#include <cuda_runtime.h>
#include <cuda_fp16.h>
#include <cstdint>
#include <cstddef>

#define NPTS 500000
#define DIM  128
#define KC   1024

// ---------------- scratch ----------------
__device__ float g_sums[KC * DIM];
__device__ float g_counts[KC];
__device__ float g_c2[KC];
__device__ __half g_cent_hi[KC * DIM];   // fp16 splits of -2*centroid
__device__ __half g_cent_mi[KC * DIM];

// ---------------- helpers ----------------
__device__ __forceinline__ uint32_t smem_u32(const void* p) {
    uint32_t a;
    asm("{ .reg .u64 t; cvta.to.shared.u64 t, %1; cvt.u32.u64 %0, t; }" : "=r"(a) : "l"(p));
    return a;
}
__device__ __forceinline__ void ldsm_x4(uint32_t* r, uint32_t addr) {
    asm volatile("ldmatrix.sync.aligned.m8n8.x4.shared.b16 {%0,%1,%2,%3}, [%4];"
        : "=r"(r[0]), "=r"(r[1]), "=r"(r[2]), "=r"(r[3]) : "r"(addr));
}
__device__ __forceinline__ void mma_f16(float* d, const uint32_t* a, uint32_t b0, uint32_t b1) {
    asm volatile("mma.sync.aligned.m16n8k16.row.col.f32.f16.f16.f32 "
        "{%0,%1,%2,%3}, {%4,%5,%6,%7}, {%8,%9}, {%0,%1,%2,%3};"
        : "+f"(d[0]), "+f"(d[1]), "+f"(d[2]), "+f"(d[3])
        : "r"(a[0]), "r"(a[1]), "r"(a[2]), "r"(a[3]), "r"(b0), "r"(b1));
}
__device__ __forceinline__ void cp16(uint32_t dst, const void* src) {
    asm volatile("cp.async.cg.shared.global [%0], [%1], 16;" :: "r"(dst), "l"(src) : "memory");
}
#define CP_COMMIT() asm volatile("cp.async.commit_group;" ::: "memory")
#define CP_WAIT0()  asm volatile("cp.async.wait_group 0;" ::: "memory")
#define CP_WAIT1()  asm volatile("cp.async.wait_group 1;" ::: "memory")
#define CP_WAIT2()  asm volatile("cp.async.wait_group 2;" ::: "memory")

// ---------------- kernel 1: zero scratch ----------------
__global__ void zero_kernel() {
    int i = blockIdx.x * blockDim.x + threadIdx.x;
    if (i < KC * DIM) g_sums[i] = 0.0f;
    if (i < KC)       g_counts[i] = 0.0f;
}

// ---------------- kernel 2: segment sum ----------------
__global__ void segsum_kernel(const float* __restrict__ vecs,
                              const int*   __restrict__ asg) {
    int gw   = (blockIdx.x * blockDim.x + threadIdx.x) >> 5;
    int lane = threadIdx.x & 31;
    if (gw >= NPTS) return;
    int k = asg[gw];
    float4 v = *((const float4*)(vecs + (size_t)gw * DIM) + lane);
    atomicAdd(((float4*)(g_sums + (size_t)k * DIM)) + lane, v);
    if (lane == 0) atomicAdd(&g_counts[k], 1.0f);
}

// ---------------- kernel 3: centroids, c2, -2c fp16 splits ----------------
__global__ void finalize_kernel(float* __restrict__ out_cent) {
    int k = blockIdx.x;
    int d = threadIdx.x;
    float c = g_sums[k * DIM + d] / g_counts[k];
    out_cent[k * DIM + d] = c;

    float m = -2.0f * c;
    __half h = __float2half_rn(m);
    __half mi = __float2half_rn(m - __half2float(h));
    g_cent_hi[k * DIM + d] = h;
    g_cent_mi[k * DIM + d] = mi;

    float s = c * c;
    #pragma unroll
    for (int o = 16; o > 0; o >>= 1) s += __shfl_down_sync(0xffffffffu, s, o);
    __shared__ float ws[4];
    if ((d & 31) == 0) ws[d >> 5] = s;
    __syncthreads();
    if (d == 0) g_c2[k] = (ws[0] + ws[1]) + (ws[2] + ws[3]);
}

// ---------------- kernel 4: mma.sync fp16-split GEMM + argmin ----------------
// 128 points/CTA x 1024 clusters. 4 warps; warp w owns points 32w..32w+31
// (two 16-row A tiles -> LDSM/MMA ratio 0.33 vs 0.5 last round).
// A: 2 fp16 splits of points, swizzled smem [2][128][256B].
// B: 2 fp16 splits of -2c, 32-cluster chunks, cp.async 3-stage pipeline.
// 3 product passes (hh, hm, mh) accumulate into fp32 D.
#define PTS_CTA 128
#define THR     128
#define CH_N    32
#define CHW     32
#define A_SPLIT 32768
#define A_OFF   0
#define B_OFF   65536
#define B_BUF   16384
#define B_SPLIT 8192
#define NBUF    3
#define C2_OFF  (B_OFF + NBUF * B_BUF)      // 114688
#define X2_OFF  (C2_OFF + KC * 4)           // 118784
#define SM_TOTAL (X2_OFF + PTS_CTA * 4)     // 119296

__device__ __forceinline__ void issue_b_chunk(uint32_t su, int tid, int ch, int buf) {
    #pragma unroll
    for (int s = 0; s < 2; s++) {
        const __half* g = (s == 0) ? g_cent_hi : g_cent_mi;
        const char* gb = (const char*)(g + (size_t)ch * CHW * DIM);
        #pragma unroll
        for (int it = 0; it < 4; it++) {
            int idx = tid + it * THR;          // 0..511
            int row = idx >> 4, kg = idx & 15;
            uint32_t dst = su + B_OFF + (uint32_t)buf * B_BUF
                         + (uint32_t)s * B_SPLIT + (uint32_t)row * 256u
                         + ((uint32_t)(kg ^ (row & 7)) << 4);
            cp16(dst, gb + (size_t)idx * 16);
        }
    }
    CP_COMMIT();
}

__global__ __launch_bounds__(THR, 2)
void argmin_mma_kernel(const float* __restrict__ vecs, float* __restrict__ out_asg) {
    extern __shared__ __align__(1024) char sm[];
    const uint32_t su = smem_u32(sm);
    float* c2s = (float*)(sm + C2_OFF);
    float* x2s = (float*)(sm + X2_OFF);
    const int tid  = threadIdx.x;
    const int lane = tid & 31;
    const int w    = tid >> 5;
    const int base = blockIdx.x * PTS_CTA;

    // ---- issue chunk 0/1 B loads first (overlaps A convert) ----
    issue_b_chunk(su, tid, 0, 0);
    issue_b_chunk(su, tid, 1, 1);

    for (int i = tid; i < KC; i += THR) c2s[i] = g_c2[i];

    // ---- A convert: fp32 -> 2x fp16 splits into swizzled smem; x2 ----
    {
        int p = tid;
        int n = base + p; if (n >= NPTS) n = NPTS - 1;
        const float4* src = (const float4*)(vecs + (size_t)n * DIM);
        float s2 = 0.0f;
        const uint32_t rowb = (uint32_t)p * 256u;
        const uint32_t psw  = (uint32_t)(p & 7);
        #pragma unroll 8
        for (int j = 0; j < 32; j++) {
            float4 v = src[j];
            int d0 = j * 4;
            #pragma unroll
            for (int q = 0; q < 2; q++) {
                float a0 = q ? v.z : v.x;
                float a1 = q ? v.w : v.y;
                int   d  = d0 + 2 * q;
                s2 = fmaf(a0, a0, s2); s2 = fmaf(a1, a1, s2);
                __half h0 = __float2half_rn(a0);
                __half m0 = __float2half_rn(a0 - __half2float(h0));
                __half h1 = __float2half_rn(a1);
                __half m1 = __float2half_rn(a1 - __half2float(h1));
                uint32_t off = rowb + ((((uint32_t)(d >> 3)) ^ psw) << 4) + (uint32_t)(d & 7) * 2u;
                __half2 ph(h0, h1), pm(m0, m1);
                *(uint32_t*)(sm + A_OFF + 0 * A_SPLIT + off) = *(uint32_t*)&ph;
                *(uint32_t*)(sm + A_OFF + 1 * A_SPLIT + off) = *(uint32_t*)&pm;
            }
        }
        x2s[p] = s2;
    }
    __syncthreads();

    const int p0 = w * 32;
    float best[2][2] = {{3.402823466e38f, 3.402823466e38f},
                        {3.402823466e38f, 3.402823466e38f}};
    int   bi[2][2]   = {{0, 0}, {0, 0}};

    uint32_t abase[2];
    #pragma unroll
    for (int mt = 0; mt < 2; mt++)
        abase[mt] = su + A_OFF + (uint32_t)(p0 + mt * 16 + (lane & 15)) * 256u;
    const uint32_t arsw0 = (uint32_t)((p0 + (lane & 15)) & 7);       // same for both mt (16 apart)
    const int akg  = lane >> 4;
    const int brow_local = ((lane >> 4) << 3) + (lane & 7);
    const int bkg_half   = (lane >> 3) & 1;

    float x2r[2][2];
    #pragma unroll
    for (int mt = 0; mt < 2; mt++) {
        x2r[mt][0] = x2s[p0 + mt * 16 + (lane >> 2)];
        x2r[mt][1] = x2s[p0 + mt * 16 + (lane >> 2) + 8];
    }

    for (int ch = 0; ch < CH_N; ch++) {
        const int buf = ch % NBUF;
        if (ch + 2 < CH_N) {
            issue_b_chunk(su, tid, ch + 2, (ch + 2) % NBUF);
            CP_WAIT2();
        } else if (ch + 1 < CH_N) {
            CP_WAIT1();
        } else {
            CP_WAIT0();
        }
        __syncthreads();

        float D[2][4][4];
        #pragma unroll
        for (int mt = 0; mt < 2; mt++)
            #pragma unroll
            for (int i = 0; i < 4; i++)
                #pragma unroll
                for (int j = 0; j < 4; j++) D[mt][i][j] = 0.0f;

        const uint32_t bbase = su + B_OFF + (uint32_t)buf * B_BUF;

        #pragma unroll
        for (int ks = 0; ks < 8; ks++) {
            uint32_t A_[2][2][4];     // [split][mt]
            {
                uint32_t ag = (uint32_t)(ks * 2 + akg);
                uint32_t asw = ((ag ^ arsw0) << 4);
                #pragma unroll
                for (int mt = 0; mt < 2; mt++) {
                    ldsm_x4(A_[0][mt], abase[mt] + 0 * A_SPLIT + asw);
                    ldsm_x4(A_[1][mt], abase[mt] + 1 * A_SPLIT + asw);
                }
            }
            uint32_t B_[2][2][4];     // [split][pp]
            #pragma unroll
            for (int pp = 0; pp < 2; pp++) {
                int r  = pp * 16 + brow_local;
                int kg = ks * 2 + bkg_half;
                uint32_t bad = bbase + (uint32_t)r * 256u + ((uint32_t)(kg ^ (r & 7)) << 4);
                ldsm_x4(B_[0][pp], bad + 0 * B_SPLIT);
                ldsm_x4(B_[1][pp], bad + 1 * B_SPLIT);
            }
            // passes: (sa,sb) = hh, hm, mh
            const int SA[3] = {0, 0, 1};
            const int SB[3] = {0, 1, 0};
            #pragma unroll
            for (int p3 = 0; p3 < 3; p3++) {
                #pragma unroll
                for (int mt = 0; mt < 2; mt++) {
                    #pragma unroll
                    for (int pp = 0; pp < 2; pp++) {
                        mma_f16(D[mt][pp * 2 + 0], A_[SA[p3]][mt], B_[SB[p3]][pp][0], B_[SB[p3]][pp][1]);
                        mma_f16(D[mt][pp * 2 + 1], A_[SA[p3]][mt], B_[SB[p3]][pp][2], B_[SB[p3]][pp][3]);
                    }
                }
            }
        }

        // ---- fold argmin (ascending cluster order within lane) ----
        #pragma unroll
        for (int nt = 0; nt < 4; nt++) {
            int cb = ch * CHW + nt * 8 + 2 * (lane & 3);
            float c20 = c2s[cb], c21 = c2s[cb + 1];
            #pragma unroll
            for (int mt = 0; mt < 2; mt++) {
                float v;
                v = (c20 + x2r[mt][0]) + D[mt][nt][0]; if (v < best[mt][0]) { best[mt][0] = v; bi[mt][0] = cb; }
                v = (c21 + x2r[mt][0]) + D[mt][nt][1]; if (v < best[mt][0]) { best[mt][0] = v; bi[mt][0] = cb + 1; }
                v = (c20 + x2r[mt][1]) + D[mt][nt][2]; if (v < best[mt][1]) { best[mt][1] = v; bi[mt][1] = cb; }
                v = (c21 + x2r[mt][1]) + D[mt][nt][3]; if (v < best[mt][1]) { best[mt][1] = v; bi[mt][1] = cb + 1; }
            }
        }
        __syncthreads();
    }

    // ---- reduce across the 4 lanes sharing each point row ----
    #pragma unroll
    for (int off = 1; off < 4; off <<= 1) {
        #pragma unroll
        for (int mt = 0; mt < 2; mt++)
            #pragma unroll
            for (int hf = 0; hf < 2; hf++) {
                float ov = __shfl_xor_sync(0xffffffffu, best[mt][hf], off);
                int   oi = __shfl_xor_sync(0xffffffffu, bi[mt][hf],   off);
                if (ov < best[mt][hf] || (ov == best[mt][hf] && oi < bi[mt][hf])) {
                    best[mt][hf] = ov; bi[mt][hf] = oi;
                }
            }
    }
    if ((lane & 3) == 0) {
        #pragma unroll
        for (int mt = 0; mt < 2; mt++) {
            int rA = p0 + mt * 16 + (lane >> 2);
            if (base + rA < NPTS)     out_asg[base + rA]     = (float)bi[mt][0];
            if (base + rA + 8 < NPTS) out_asg[base + rA + 8] = (float)bi[mt][1];
        }
    }
}

// ---------------- launch ----------------
extern "C" void kernel_launch(void* const* d_in, const int* in_sizes, int n_in,
                              void* d_out, int out_size) {
    const float* vecs = (const float*)d_in[0];
    const int*   asg  = (const int*)d_in[1];
    float* out      = (float*)d_out;
    float* out_cent = out;             // [KC*DIM]
    float* out_asg  = out + KC * DIM;  // [NPTS]

    zero_kernel<<<(KC * DIM + 255) / 256, 256>>>();
    segsum_kernel<<<(NPTS * 32) / 256, 256>>>(vecs, asg);
    finalize_kernel<<<KC, DIM>>>(out_cent);

    cudaFuncSetAttribute(argmin_mma_kernel,
                         cudaFuncAttributeMaxDynamicSharedMemorySize, SM_TOTAL);
    int ablocks = (NPTS + PTS_CTA - 1) / PTS_CTA;
    argmin_mma_kernel<<<ablocks, THR, SM_TOTAL>>>(vecs, out_asg);
}

// round 9
// speedup vs baseline: 1.1895x; 1.1895x over previous
#include <cuda_runtime.h>
#include <cuda_fp16.h>
#include <cstdint>
#include <cstddef>

#define NPTS 500000
#define DIM  128
#define KC   1024

// ---------------- scratch ----------------
__device__ float g_sums[KC * DIM];
__device__ float g_counts[KC];
__device__ float g_c2[KC];
__device__ __half g_cent_hi[KC * DIM];   // fp16 splits of -2*centroid
__device__ __half g_cent_mi[KC * DIM];

// ---------------- helpers ----------------
__device__ __forceinline__ uint32_t smem_u32(const void* p) {
    uint32_t a;
    asm("{ .reg .u64 t; cvta.to.shared.u64 t, %1; cvt.u32.u64 %0, t; }" : "=r"(a) : "l"(p));
    return a;
}
__device__ __forceinline__ void ldsm_x4(uint32_t* r, uint32_t addr) {
    asm volatile("ldmatrix.sync.aligned.m8n8.x4.shared.b16 {%0,%1,%2,%3}, [%4];"
        : "=r"(r[0]), "=r"(r[1]), "=r"(r[2]), "=r"(r[3]) : "r"(addr));
}
__device__ __forceinline__ void mma_f16(float* d, const uint32_t* a, uint32_t b0, uint32_t b1) {
    asm volatile("mma.sync.aligned.m16n8k16.row.col.f32.f16.f16.f32 "
        "{%0,%1,%2,%3}, {%4,%5,%6,%7}, {%8,%9}, {%0,%1,%2,%3};"
        : "+f"(d[0]), "+f"(d[1]), "+f"(d[2]), "+f"(d[3])
        : "r"(a[0]), "r"(a[1]), "r"(a[2]), "r"(a[3]), "r"(b0), "r"(b1));
}
__device__ __forceinline__ void cp16(uint32_t dst, const void* src) {
    asm volatile("cp.async.cg.shared.global [%0], [%1], 16;" :: "r"(dst), "l"(src) : "memory");
}
#define CP_COMMIT() asm volatile("cp.async.commit_group;" ::: "memory")
#define CP_WAIT0()  asm volatile("cp.async.wait_group 0;" ::: "memory")
#define CP_WAIT1()  asm volatile("cp.async.wait_group 1;" ::: "memory")

// ---------------- kernel 1: zero scratch ----------------
__global__ void zero_kernel() {
    int i = blockIdx.x * blockDim.x + threadIdx.x;
    if (i < KC * DIM) g_sums[i] = 0.0f;
    if (i < KC)       g_counts[i] = 0.0f;
}

// ---------------- kernel 2: segment sum ----------------
__global__ void segsum_kernel(const float* __restrict__ vecs,
                              const int*   __restrict__ asg) {
    int gw   = (blockIdx.x * blockDim.x + threadIdx.x) >> 5;
    int lane = threadIdx.x & 31;
    if (gw >= NPTS) return;
    int k = asg[gw];
    float4 v = *((const float4*)(vecs + (size_t)gw * DIM) + lane);
    atomicAdd(((float4*)(g_sums + (size_t)k * DIM)) + lane, v);
    if (lane == 0) atomicAdd(&g_counts[k], 1.0f);
}

// ---------------- kernel 3: centroids, c2, -2c fp16 splits ----------------
__global__ void finalize_kernel(float* __restrict__ out_cent) {
    int k = blockIdx.x;
    int d = threadIdx.x;
    float c = g_sums[k * DIM + d] / g_counts[k];
    out_cent[k * DIM + d] = c;

    float m = -2.0f * c;
    __half h = __float2half_rn(m);
    __half mi = __float2half_rn(m - __half2float(h));
    g_cent_hi[k * DIM + d] = h;
    g_cent_mi[k * DIM + d] = mi;

    float s = c * c;
    #pragma unroll
    for (int o = 16; o > 0; o >>= 1) s += __shfl_down_sync(0xffffffffu, s, o);
    __shared__ float ws[4];
    if ((d & 31) == 0) ws[d >> 5] = s;
    __syncthreads();
    if (d == 0) g_c2[k] = (ws[0] + ws[1]) + (ws[2] + ws[3]);
}

// ---------------- kernel 4: mma.sync fp16-split GEMM + argmin ----------------
// 128 points/CTA x 1024 clusters. 4 warps; warp w owns points 32w..32w+31
// (two 16-row A tiles -> LDSM/MMA ratio 0.33).
// A: 2 fp16 splits of points, swizzled smem [2][128][256B].
// B: 2 fp16 splits of -2c, 32-cluster chunks, cp.async double-buffered.
// 3 product passes (hh, hm, mh) accumulate into fp32 D.
// smem ~103KB -> 2 CTAs/SM.
#define PTS_CTA 128
#define THR     128
#define CH_N    32
#define CHW     32
#define A_SPLIT 32768
#define A_OFF   0
#define B_OFF   65536
#define B_BUF   16384
#define B_SPLIT 8192
#define NBUF    2
#define C2_OFF  (B_OFF + NBUF * B_BUF)      // 98304
#define X2_OFF  (C2_OFF + KC * 4)           // 102400
#define SM_TOTAL (X2_OFF + PTS_CTA * 4)     // 102912

__device__ __forceinline__ void issue_b_chunk(uint32_t su, int tid, int ch, int buf) {
    #pragma unroll
    for (int s = 0; s < 2; s++) {
        const __half* g = (s == 0) ? g_cent_hi : g_cent_mi;
        const char* gb = (const char*)(g + (size_t)ch * CHW * DIM);
        #pragma unroll
        for (int it = 0; it < 4; it++) {
            int idx = tid + it * THR;          // 0..511
            int row = idx >> 4, kg = idx & 15;
            uint32_t dst = su + B_OFF + (uint32_t)buf * B_BUF
                         + (uint32_t)s * B_SPLIT + (uint32_t)row * 256u
                         + ((uint32_t)(kg ^ (row & 7)) << 4);
            cp16(dst, gb + (size_t)idx * 16);
        }
    }
    CP_COMMIT();
}

__global__ __launch_bounds__(THR, 2)
void argmin_mma_kernel(const float* __restrict__ vecs, float* __restrict__ out_asg) {
    extern __shared__ __align__(1024) char sm[];
    const uint32_t su = smem_u32(sm);
    float* c2s = (float*)(sm + C2_OFF);
    float* x2s = (float*)(sm + X2_OFF);
    const int tid  = threadIdx.x;
    const int lane = tid & 31;
    const int w    = tid >> 5;
    const int base = blockIdx.x * PTS_CTA;

    // ---- issue chunk 0 B loads first (overlaps A convert) ----
    issue_b_chunk(su, tid, 0, 0);

    for (int i = tid; i < KC; i += THR) c2s[i] = g_c2[i];

    // ---- A convert: fp32 -> 2x fp16 splits into swizzled smem; x2 ----
    // NOTE: x2 arithmetic order is frozen to the validated round-5/7 form:
    // two serial 64-dim fmaf chains (dims 0..63 and 64..127), then one add.
    {
        int p = tid;
        int n = base + p; if (n >= NPTS) n = NPTS - 1;
        const uint32_t rowb = (uint32_t)p * 256u;
        const uint32_t psw  = (uint32_t)(p & 7);
        float s2h[2];
        #pragma unroll
        for (int h = 0; h < 2; h++) {
            const float4* src = (const float4*)(vecs + (size_t)n * DIM) + h * 16;
            float s2 = 0.0f;
            #pragma unroll
            for (int j = 0; j < 16; j++) {
                float4 v = src[j];
                int d0 = h * 64 + j * 4;
                #pragma unroll
                for (int q = 0; q < 2; q++) {
                    float a0 = q ? v.z : v.x;
                    float a1 = q ? v.w : v.y;
                    int   d  = d0 + 2 * q;
                    s2 = fmaf(a0, a0, s2); s2 = fmaf(a1, a1, s2);
                    __half h0 = __float2half_rn(a0);
                    __half m0 = __float2half_rn(a0 - __half2float(h0));
                    __half h1 = __float2half_rn(a1);
                    __half m1 = __float2half_rn(a1 - __half2float(h1));
                    uint32_t off = rowb + ((((uint32_t)(d >> 3)) ^ psw) << 4) + (uint32_t)(d & 7) * 2u;
                    __half2 ph(h0, h1), pm(m0, m1);
                    *(uint32_t*)(sm + A_OFF + 0 * A_SPLIT + off) = *(uint32_t*)&ph;
                    *(uint32_t*)(sm + A_OFF + 1 * A_SPLIT + off) = *(uint32_t*)&pm;
                }
            }
            s2h[h] = s2;
        }
        x2s[p] = s2h[0] + s2h[1];
    }
    __syncthreads();

    const int p0 = w * 32;
    float best[2][2] = {{3.402823466e38f, 3.402823466e38f},
                        {3.402823466e38f, 3.402823466e38f}};
    int   bi[2][2]   = {{0, 0}, {0, 0}};

    uint32_t abase[2];
    #pragma unroll
    for (int mt = 0; mt < 2; mt++)
        abase[mt] = su + A_OFF + (uint32_t)(p0 + mt * 16 + (lane & 15)) * 256u;
    const uint32_t arsw0 = (uint32_t)((p0 + (lane & 15)) & 7);   // same for both mt (16 apart)
    const int akg  = lane >> 4;
    const int brow_local = ((lane >> 4) << 3) + (lane & 7);
    const int bkg_half   = (lane >> 3) & 1;

    float x2r[2][2];
    #pragma unroll
    for (int mt = 0; mt < 2; mt++) {
        x2r[mt][0] = x2s[p0 + mt * 16 + (lane >> 2)];
        x2r[mt][1] = x2s[p0 + mt * 16 + (lane >> 2) + 8];
    }

    for (int ch = 0; ch < CH_N; ch++) {
        const int buf = ch & 1;
        if (ch + 1 < CH_N) {
            issue_b_chunk(su, tid, ch + 1, buf ^ 1);
            CP_WAIT1();
        } else {
            CP_WAIT0();
        }
        __syncthreads();

        float D[2][4][4];
        #pragma unroll
        for (int mt = 0; mt < 2; mt++)
            #pragma unroll
            for (int i = 0; i < 4; i++)
                #pragma unroll
                for (int j = 0; j < 4; j++) D[mt][i][j] = 0.0f;

        const uint32_t bbase = su + B_OFF + (uint32_t)buf * B_BUF;

        #pragma unroll
        for (int ks = 0; ks < 8; ks++) {
            uint32_t A_[2][2][4];     // [split][mt]
            {
                uint32_t ag = (uint32_t)(ks * 2 + akg);
                uint32_t asw = ((ag ^ arsw0) << 4);
                #pragma unroll
                for (int mt = 0; mt < 2; mt++) {
                    ldsm_x4(A_[0][mt], abase[mt] + 0 * A_SPLIT + asw);
                    ldsm_x4(A_[1][mt], abase[mt] + 1 * A_SPLIT + asw);
                }
            }
            uint32_t B_[2][2][4];     // [split][pp]
            #pragma unroll
            for (int pp = 0; pp < 2; pp++) {
                int r  = pp * 16 + brow_local;
                int kg = ks * 2 + bkg_half;
                uint32_t bad = bbase + (uint32_t)r * 256u + ((uint32_t)(kg ^ (r & 7)) << 4);
                ldsm_x4(B_[0][pp], bad + 0 * B_SPLIT);
                ldsm_x4(B_[1][pp], bad + 1 * B_SPLIT);
            }
            // passes: (sa,sb) = hh, hm, mh
            const int SA[3] = {0, 0, 1};
            const int SB[3] = {0, 1, 0};
            #pragma unroll
            for (int p3 = 0; p3 < 3; p3++) {
                #pragma unroll
                for (int mt = 0; mt < 2; mt++) {
                    #pragma unroll
                    for (int pp = 0; pp < 2; pp++) {
                        mma_f16(D[mt][pp * 2 + 0], A_[SA[p3]][mt], B_[SB[p3]][pp][0], B_[SB[p3]][pp][1]);
                        mma_f16(D[mt][pp * 2 + 1], A_[SA[p3]][mt], B_[SB[p3]][pp][2], B_[SB[p3]][pp][3]);
                    }
                }
            }
        }

        // ---- fold argmin (ascending cluster order within lane) ----
        #pragma unroll
        for (int nt = 0; nt < 4; nt++) {
            int cb = ch * CHW + nt * 8 + 2 * (lane & 3);
            float c20 = c2s[cb], c21 = c2s[cb + 1];
            #pragma unroll
            for (int mt = 0; mt < 2; mt++) {
                float v;
                v = (c20 + x2r[mt][0]) + D[mt][nt][0]; if (v < best[mt][0]) { best[mt][0] = v; bi[mt][0] = cb; }
                v = (c21 + x2r[mt][0]) + D[mt][nt][1]; if (v < best[mt][0]) { best[mt][0] = v; bi[mt][0] = cb + 1; }
                v = (c20 + x2r[mt][1]) + D[mt][nt][2]; if (v < best[mt][1]) { best[mt][1] = v; bi[mt][1] = cb; }
                v = (c21 + x2r[mt][1]) + D[mt][nt][3]; if (v < best[mt][1]) { best[mt][1] = v; bi[mt][1] = cb + 1; }
            }
        }
        __syncthreads();
    }

    // ---- reduce across the 4 lanes sharing each point row ----
    #pragma unroll
    for (int off = 1; off < 4; off <<= 1) {
        #pragma unroll
        for (int mt = 0; mt < 2; mt++)
            #pragma unroll
            for (int hf = 0; hf < 2; hf++) {
                float ov = __shfl_xor_sync(0xffffffffu, best[mt][hf], off);
                int   oi = __shfl_xor_sync(0xffffffffu, bi[mt][hf],   off);
                if (ov < best[mt][hf] || (ov == best[mt][hf] && oi < bi[mt][hf])) {
                    best[mt][hf] = ov; bi[mt][hf] = oi;
                }
            }
    }
    if ((lane & 3) == 0) {
        #pragma unroll
        for (int mt = 0; mt < 2; mt++) {
            int rA = p0 + mt * 16 + (lane >> 2);
            if (base + rA < NPTS)     out_asg[base + rA]     = (float)bi[mt][0];
            if (base + rA + 8 < NPTS) out_asg[base + rA + 8] = (float)bi[mt][1];
        }
    }
}

// ---------------- launch ----------------
extern "C" void kernel_launch(void* const* d_in, const int* in_sizes, int n_in,
                              void* d_out, int out_size) {
    const float* vecs = (const float*)d_in[0];
    const int*   asg  = (const int*)d_in[1];
    float* out      = (float*)d_out;
    float* out_cent = out;             // [KC*DIM]
    float* out_asg  = out + KC * DIM;  // [NPTS]

    zero_kernel<<<(KC * DIM + 255) / 256, 256>>>();
    segsum_kernel<<<(NPTS * 32) / 256, 256>>>(vecs, asg);
    finalize_kernel<<<KC, DIM>>>(out_cent);

    cudaFuncSetAttribute(argmin_mma_kernel,
                         cudaFuncAttributeMaxDynamicSharedMemorySize, SM_TOTAL);
    int ablocks = (NPTS + PTS_CTA - 1) / PTS_CTA;
    argmin_mma_kernel<<<ablocks, THR, SM_TOTAL>>>(vecs, out_asg);
}